// round 8
// baseline (speedup 1.0000x reference)
#include <cuda_runtime.h>
#include <cuda_bf16.h>
#include <math_constants.h>

// Problem constants
#define BATCH 2
#define SEQ   2048
#define EMBD  2048
#define NHEAD 16
#define NKV   4
#define HDIM  128
#define GROUP (NHEAD / NKV)          // 4
#define ROWS  (BATCH * SEQ)          // 4096
#define RMS_EPS 1.1920928955078125e-07f
#define ATTN_SCALE 0.08838834764831845f  // 1/sqrt(128)

// ---------------- scratch (device globals; no allocations allowed) ----------
__device__ float g_q[ROWS * NHEAD * HDIM];   // [B*T, 16, 128]
__device__ float g_k[ROWS * NKV * HDIM];     // [B*T, 4, 128]
__device__ float g_v[ROWS * NKV * HDIM];
__device__ float g_y[ROWS * EMBD];           // attention output [B*T, C]

// ---------------- SGEMM: C[M,N] = A[M,K] @ B[N,K]^T ------------------------
// 64x64 block tile, BK=16, 256 threads, 4x4 per thread.
#define BM 64
#define BN 64
#define BK 16

__global__ void gemm_abt(const float* __restrict__ A,
                         const float* __restrict__ Bw,
                         float* __restrict__ C,
                         int M, int N, int K) {
    __shared__ float As[BK][BM];
    __shared__ float Bs[BK][BN];

    const int tid = threadIdx.x;          // 0..255
    const int tx  = tid & 15;             // 0..15
    const int ty  = tid >> 4;             // 0..15
    const int m0  = blockIdx.y * BM;
    const int n0  = blockIdx.x * BN;

    const int lrow = tid >> 2;            // 0..63
    const int lk   = (tid & 3) * 4;       // 0,4,8,12

    float acc[4][4];
#pragma unroll
    for (int i = 0; i < 4; i++)
#pragma unroll
        for (int j = 0; j < 4; j++) acc[i][j] = 0.0f;

    for (int k0 = 0; k0 < K; k0 += BK) {
        float4 a  = *(const float4*)&A [(size_t)(m0 + lrow) * K + k0 + lk];
        float4 bv = *(const float4*)&Bw[(size_t)(n0 + lrow) * K + k0 + lk];
        __syncthreads();   // previous compute done
        As[lk + 0][lrow] = a.x;  As[lk + 1][lrow] = a.y;
        As[lk + 2][lrow] = a.z;  As[lk + 3][lrow] = a.w;
        Bs[lk + 0][lrow] = bv.x; Bs[lk + 1][lrow] = bv.y;
        Bs[lk + 2][lrow] = bv.z; Bs[lk + 3][lrow] = bv.w;
        __syncthreads();   // smem ready

#pragma unroll
        for (int k = 0; k < BK; k++) {
            float4 ra = *(const float4*)&As[k][ty * 4];
            float4 rb = *(const float4*)&Bs[k][tx * 4];
            acc[0][0] += ra.x * rb.x; acc[0][1] += ra.x * rb.y;
            acc[0][2] += ra.x * rb.z; acc[0][3] += ra.x * rb.w;
            acc[1][0] += ra.y * rb.x; acc[1][1] += ra.y * rb.y;
            acc[1][2] += ra.y * rb.z; acc[1][3] += ra.y * rb.w;
            acc[2][0] += ra.z * rb.x; acc[2][1] += ra.z * rb.y;
            acc[2][2] += ra.z * rb.z; acc[2][3] += ra.z * rb.w;
            acc[3][0] += ra.w * rb.x; acc[3][1] += ra.w * rb.y;
            acc[3][2] += ra.w * rb.z; acc[3][3] += ra.w * rb.w;
        }
    }

#pragma unroll
    for (int i = 0; i < 4; i++) {
        float4 out;
        out.x = acc[i][0]; out.y = acc[i][1]; out.z = acc[i][2]; out.w = acc[i][3];
        *(float4*)&C[(size_t)(m0 + ty * 4 + i) * N + n0 + tx * 4] = out;
    }
}

// ---------------- fused RoPE + RMSNorm --------------------------------------
// grid: (B*T, H); 128 threads (one per dim).
__global__ void rope_rms(float* __restrict__ buf,
                         const float* __restrict__ cosv,
                         const float* __restrict__ sinv,
                         int H) {
    const int row = blockIdx.x;            // 0..B*T-1
    const int h   = blockIdx.y;
    const int d   = threadIdx.x;           // 0..127
    const int t   = row & (SEQ - 1);       // token position within sequence

    float* p = buf + (((size_t)row * H + h) << 7);
    float x = p[d];
    float other = (d < 64) ? -p[d + 64] : p[d - 64];
    float r = x * cosv[t * HDIM + d] + other * sinv[t * HDIM + d];

    // block reduce of r*r over 128 threads (4 warps)
    __shared__ float red[4];
    float s = r * r;
#pragma unroll
    for (int o = 16; o; o >>= 1) s += __shfl_xor_sync(0xffffffffu, s, o);
    if ((d & 31) == 0) red[d >> 5] = s;
    __syncthreads();
    float tot = red[0] + red[1] + red[2] + red[3];
    float inv = rsqrtf(tot * (1.0f / HDIM) + RMS_EPS);
    p[d] = r * inv;
}

// ---------------- flash attention (causal, GQA) ------------------------------
// grid: (T/QROWS, NHEAD, B); 256 threads = 8 warps; one q-row per warp.
#define QROWS 8
#define KTILE 32

__global__ void attn_fwd(const float* __restrict__ qb,
                         const float* __restrict__ kb,
                         const float* __restrict__ vb,
                         float* __restrict__ yb) {
    const int warp = threadIdx.x >> 5;   // 0..7
    const int lane = threadIdx.x & 31;
    const int qblk = blockIdx.x;
    const int h    = blockIdx.y;
    const int b    = blockIdx.z;
    const int g    = h >> 2;             // kv head = h / GROUP
    const int qrow = qblk * QROWS + warp;

    __shared__ float Ks[KTILE][HDIM];
    __shared__ float Vs[KTILE][HDIM];

    const float* qp = qb + ((((size_t)b * SEQ + qrow) * NHEAD + h) << 7);
    const float q0 = qp[lane], q1 = qp[lane + 32],
                q2 = qp[lane + 64], q3 = qp[lane + 96];

    float acc0 = 0.f, acc1 = 0.f, acc2 = 0.f, acc3 = 0.f;
    float m = -CUDART_INF_F, lsum = 0.f;

    const int kmax = qblk * QROWS + QROWS - 1;   // block-max key index

    for (int k0 = 0; k0 <= kmax; k0 += KTILE) {
        __syncthreads();  // previous tile consumed
        // load KTILE keys * 128 dims of K and V (float4 granularity)
        for (int i = threadIdx.x; i < KTILE * (HDIM / 4); i += 256) {
            int key = i >> 5;            // HDIM/4 = 32 float4 per key
            int dd  = (i & 31) * 4;
            size_t base = ((((size_t)b * SEQ + k0 + key) * NKV + g) << 7) + dd;
            *(float4*)&Ks[key][dd] = *(const float4*)&kb[base];
            *(float4*)&Vs[key][dd] = *(const float4*)&vb[base];
        }
        __syncthreads();

        int jend = min(KTILE, qrow - k0 + 1);    // causal bound (may be <=0)
        for (int j = 0; j < jend; j++) {
            float s = q0 * Ks[j][lane]      + q1 * Ks[j][lane + 32]
                    + q2 * Ks[j][lane + 64] + q3 * Ks[j][lane + 96];
#pragma unroll
            for (int o = 16; o; o >>= 1) s += __shfl_xor_sync(0xffffffffu, s, o);
            s *= ATTN_SCALE;
            float mnew = fmaxf(m, s);
            float corr = __expf(m - mnew);
            float p    = __expf(s - mnew);
            lsum = lsum * corr + p;
            acc0 = acc0 * corr + p * Vs[j][lane];
            acc1 = acc1 * corr + p * Vs[j][lane + 32];
            acc2 = acc2 * corr + p * Vs[j][lane + 64];
            acc3 = acc3 * corr + p * Vs[j][lane + 96];
            m = mnew;
        }
    }

    float inv = 1.0f / lsum;
    float* yp = yb + ((((size_t)b * SEQ + qrow) * NHEAD + h) << 7);
    yp[lane]      = acc0 * inv;
    yp[lane + 32] = acc1 * inv;
    yp[lane + 64] = acc2 * inv;
    yp[lane + 96] = acc3 * inv;
}

// ---------------- launch ------------------------------------------------------
extern "C" void kernel_launch(void* const* d_in, const int* in_sizes, int n_in,
                              void* d_out, int out_size) {
    const float* x     = (const float*)d_in[0];   // [2,2048,2048]
    const float* cosv  = (const float*)d_in[1];   // [2048,1,128]
    const float* sinv  = (const float*)d_in[2];
    const float* wq    = (const float*)d_in[3];   // [2048,2048]
    const float* wk    = (const float*)d_in[4];   // [512,2048]
    const float* wv    = (const float*)d_in[5];   // [512,2048]
    const float* wproj = (const float*)d_in[6];   // [2048,2048]
    float* out = (float*)d_out;

    float *qp, *kp, *vp, *yp;
    cudaGetSymbolAddress((void**)&qp, g_q);
    cudaGetSymbolAddress((void**)&kp, g_k);
    cudaGetSymbolAddress((void**)&vp, g_v);
    cudaGetSymbolAddress((void**)&yp, g_y);

    // QKV projections
    {
        dim3 gq(EMBD / BN, ROWS / BM);
        gemm_abt<<<gq, 256>>>(x, wq, qp, ROWS, EMBD, EMBD);
        dim3 gk((NKV * HDIM) / BN, ROWS / BM);
        gemm_abt<<<gk, 256>>>(x, wk, kp, ROWS, NKV * HDIM, EMBD);
        gemm_abt<<<gk, 256>>>(x, wv, vp, ROWS, NKV * HDIM, EMBD);
    }

    // RoPE + RMSNorm on q and k
    {
        dim3 grq(ROWS, NHEAD);
        rope_rms<<<grq, HDIM>>>(qp, cosv, sinv, NHEAD);
        dim3 grk(ROWS, NKV);
        rope_rms<<<grk, HDIM>>>(kp, cosv, sinv, NKV);
    }

    // attention
    {
        dim3 ga(SEQ / QROWS, NHEAD, BATCH);
        attn_fwd<<<ga, 256>>>(qp, kp, vp, yp);
    }

    // output projection
    {
        dim3 gp(EMBD / BN, ROWS / BM);
        gemm_abt<<<gp, 256>>>(yp, wproj, out, ROWS, EMBD, EMBD);
    }
}

// round 11
// speedup vs baseline: 1.0048x; 1.0048x over previous
#include <cuda_runtime.h>
#include <cuda_bf16.h>
#include <math_constants.h>

// Problem constants
#define BATCH 2
#define SEQ   2048
#define EMBD  2048
#define NHEAD 16
#define NKV   4
#define HDIM  128
#define GROUP (NHEAD / NKV)          // 4
#define ROWS  (BATCH * SEQ)          // 4096
#define RMS_EPS 1.1920928955078125e-07f
#define ATTN_SCALE 0.08838834764831845f  // 1/sqrt(128)

// ---------------- scratch (device globals; no allocations allowed) ----------
__device__ float g_q[ROWS * NHEAD * HDIM];   // [B*T, 16, 128]
__device__ float g_k[ROWS * NKV * HDIM];     // [B*T, 4, 128]
__device__ float g_v[ROWS * NKV * HDIM];
__device__ float g_y[ROWS * EMBD];           // attention output [B*T, C]

// ---------------- SGEMM: C[M,N] = A[M,K] @ B[N,K]^T ------------------------
// 64x64 block tile, BK=16, 256 threads, 4x4 per thread.
#define BM 64
#define BN 64
#define BK 16

__global__ void gemm_abt(const float* __restrict__ A,
                         const float* __restrict__ Bw,
                         float* __restrict__ C,
                         int M, int N, int K) {
    __shared__ float As[BK][BM];
    __shared__ float Bs[BK][BN];

    const int tid = threadIdx.x;          // 0..255
    const int tx  = tid & 15;             // 0..15
    const int ty  = tid >> 4;             // 0..15
    const int m0  = blockIdx.y * BM;
    const int n0  = blockIdx.x * BN;

    const int lrow = tid >> 2;            // 0..63
    const int lk   = (tid & 3) * 4;       // 0,4,8,12

    float acc[4][4];
#pragma unroll
    for (int i = 0; i < 4; i++)
#pragma unroll
        for (int j = 0; j < 4; j++) acc[i][j] = 0.0f;

    for (int k0 = 0; k0 < K; k0 += BK) {
        float4 a  = *(const float4*)&A [(size_t)(m0 + lrow) * K + k0 + lk];
        float4 bv = *(const float4*)&Bw[(size_t)(n0 + lrow) * K + k0 + lk];
        __syncthreads();   // previous compute done
        As[lk + 0][lrow] = a.x;  As[lk + 1][lrow] = a.y;
        As[lk + 2][lrow] = a.z;  As[lk + 3][lrow] = a.w;
        Bs[lk + 0][lrow] = bv.x; Bs[lk + 1][lrow] = bv.y;
        Bs[lk + 2][lrow] = bv.z; Bs[lk + 3][lrow] = bv.w;
        __syncthreads();   // smem ready

#pragma unroll
        for (int k = 0; k < BK; k++) {
            float4 ra = *(const float4*)&As[k][ty * 4];
            float4 rb = *(const float4*)&Bs[k][tx * 4];
            acc[0][0] += ra.x * rb.x; acc[0][1] += ra.x * rb.y;
            acc[0][2] += ra.x * rb.z; acc[0][3] += ra.x * rb.w;
            acc[1][0] += ra.y * rb.x; acc[1][1] += ra.y * rb.y;
            acc[1][2] += ra.y * rb.z; acc[1][3] += ra.y * rb.w;
            acc[2][0] += ra.z * rb.x; acc[2][1] += ra.z * rb.y;
            acc[2][2] += ra.z * rb.z; acc[2][3] += ra.z * rb.w;
            acc[3][0] += ra.w * rb.x; acc[3][1] += ra.w * rb.y;
            acc[3][2] += ra.w * rb.z; acc[3][3] += ra.w * rb.w;
        }
    }

#pragma unroll
    for (int i = 0; i < 4; i++) {
        float4 out;
        out.x = acc[i][0]; out.y = acc[i][1]; out.z = acc[i][2]; out.w = acc[i][3];
        *(float4*)&C[(size_t)(m0 + ty * 4 + i) * N + n0 + tx * 4] = out;
    }
}

// ---------------- fused RoPE + RMSNorm --------------------------------------
// grid: (B*T, H); 128 threads (one per dim).
__global__ void rope_rms(float* __restrict__ buf,
                         const float* __restrict__ cosv,
                         const float* __restrict__ sinv,
                         int H) {
    const int row = blockIdx.x;            // 0..B*T-1
    const int h   = blockIdx.y;
    const int d   = threadIdx.x;           // 0..127
    const int t   = row & (SEQ - 1);       // token position within sequence

    float* p = buf + (((size_t)row * H + h) << 7);
    float x = p[d];
    float other = (d < 64) ? -p[d + 64] : p[d - 64];
    float r = x * cosv[t * HDIM + d] + other * sinv[t * HDIM + d];

    // block reduce of r*r over 128 threads (4 warps)
    __shared__ float red[4];
    float s = r * r;
#pragma unroll
    for (int o = 16; o; o >>= 1) s += __shfl_xor_sync(0xffffffffu, s, o);
    if ((d & 31) == 0) red[d >> 5] = s;
    __syncthreads();
    float tot = red[0] + red[1] + red[2] + red[3];
    float inv = rsqrtf(tot * (1.0f / HDIM) + RMS_EPS);
    p[d] = r * inv;
}

// ---------------- flash attention (causal, GQA) ------------------------------
// grid: (T/QROWS, NHEAD, B); 256 threads = 8 warps; one q-row per warp.
#define QROWS 8
#define KTILE 32

__global__ void attn_fwd(const float* __restrict__ qb,
                         const float* __restrict__ kb,
                         const float* __restrict__ vb,
                         float* __restrict__ yb) {
    const int warp = threadIdx.x >> 5;   // 0..7
    const int lane = threadIdx.x & 31;
    const int qblk = blockIdx.x;
    const int h    = blockIdx.y;
    const int b    = blockIdx.z;
    const int g    = h >> 2;             // kv head = h / GROUP
    const int qrow = qblk * QROWS + warp;

    __shared__ float Ks[KTILE][HDIM];
    __shared__ float Vs[KTILE][HDIM];

    const float* qp = qb + ((((size_t)b * SEQ + qrow) * NHEAD + h) << 7);
    const float q0 = qp[lane], q1 = qp[lane + 32],
                q2 = qp[lane + 64], q3 = qp[lane + 96];

    float acc0 = 0.f, acc1 = 0.f, acc2 = 0.f, acc3 = 0.f;
    float m = -CUDART_INF_F, lsum = 0.f;

    const int kmax = qblk * QROWS + QROWS - 1;   // block-max key index

    for (int k0 = 0; k0 <= kmax; k0 += KTILE) {
        __syncthreads();  // previous tile consumed
        // load KTILE keys * 128 dims of K and V (float4 granularity)
        for (int i = threadIdx.x; i < KTILE * (HDIM / 4); i += 256) {
            int key = i >> 5;            // HDIM/4 = 32 float4 per key
            int dd  = (i & 31) * 4;
            size_t base = ((((size_t)b * SEQ + k0 + key) * NKV + g) << 7) + dd;
            *(float4*)&Ks[key][dd] = *(const float4*)&kb[base];
            *(float4*)&Vs[key][dd] = *(const float4*)&vb[base];
        }
        __syncthreads();

        int jend = min(KTILE, qrow - k0 + 1);    // causal bound (may be <=0)
        for (int j = 0; j < jend; j++) {
            float s = q0 * Ks[j][lane]      + q1 * Ks[j][lane + 32]
                    + q2 * Ks[j][lane + 64] + q3 * Ks[j][lane + 96];
#pragma unroll
            for (int o = 16; o; o >>= 1) s += __shfl_xor_sync(0xffffffffu, s, o);
            s *= ATTN_SCALE;
            float mnew = fmaxf(m, s);
            float corr = __expf(m - mnew);
            float p    = __expf(s - mnew);
            lsum = lsum * corr + p;
            acc0 = acc0 * corr + p * Vs[j][lane];
            acc1 = acc1 * corr + p * Vs[j][lane + 32];
            acc2 = acc2 * corr + p * Vs[j][lane + 64];
            acc3 = acc3 * corr + p * Vs[j][lane + 96];
            m = mnew;
        }
    }

    float inv = 1.0f / lsum;
    float* yp = yb + ((((size_t)b * SEQ + qrow) * NHEAD + h) << 7);
    yp[lane]      = acc0 * inv;
    yp[lane + 32] = acc1 * inv;
    yp[lane + 64] = acc2 * inv;
    yp[lane + 96] = acc3 * inv;
}

// ---------------- launch ------------------------------------------------------
extern "C" void kernel_launch(void* const* d_in, const int* in_sizes, int n_in,
                              void* d_out, int out_size) {
    const float* x     = (const float*)d_in[0];   // [2,2048,2048]
    const float* cosv  = (const float*)d_in[1];   // [2048,1,128]
    const float* sinv  = (const float*)d_in[2];
    const float* wq    = (const float*)d_in[3];   // [2048,2048]
    const float* wk    = (const float*)d_in[4];   // [512,2048]
    const float* wv    = (const float*)d_in[5];   // [512,2048]
    const float* wproj = (const float*)d_in[6];   // [2048,2048]
    float* out = (float*)d_out;

    float *qp, *kp, *vp, *yp;
    cudaGetSymbolAddress((void**)&qp, g_q);
    cudaGetSymbolAddress((void**)&kp, g_k);
    cudaGetSymbolAddress((void**)&vp, g_v);
    cudaGetSymbolAddress((void**)&yp, g_y);

    // QKV projections
    {
        dim3 gq(EMBD / BN, ROWS / BM);
        gemm_abt<<<gq, 256>>>(x, wq, qp, ROWS, EMBD, EMBD);
        dim3 gk((NKV * HDIM) / BN, ROWS / BM);
        gemm_abt<<<gk, 256>>>(x, wk, kp, ROWS, NKV * HDIM, EMBD);
        gemm_abt<<<gk, 256>>>(x, wv, vp, ROWS, NKV * HDIM, EMBD);
    }

    // RoPE + RMSNorm on q and k
    {
        dim3 grq(ROWS, NHEAD);
        rope_rms<<<grq, HDIM>>>(qp, cosv, sinv, NHEAD);
        dim3 grk(ROWS, NKV);
        rope_rms<<<grk, HDIM>>>(kp, cosv, sinv, NKV);
    }

    // attention
    {
        dim3 ga(SEQ / QROWS, NHEAD, BATCH);
        attn_fwd<<<ga, 256>>>(qp, kp, vp, yp);
    }

    // output projection
    {
        dim3 gp(EMBD / BN, ROWS / BM);
        gemm_abt<<<gp, 256>>>(yp, wproj, out, ROWS, EMBD, EMBD);
    }
}